// round 6
// baseline (speedup 1.0000x reference)
#include <cuda_runtime.h>

// LSTM_71683004170991 — only batch element B-1 contributes to the output.
// Single-warp serial scan (T=512, H=16) with ALL FOUR gates per lo-lane:
// zero shfls in the scan loop; c-update is fully lane-local. Joint (i,f)/(g,o)
// f32x2 accumulation seeded directly by xp quads. Phase-1 xp precompute
// overlaps the scan via a chunk-0 ready flag (producer warps 1..11).

typedef unsigned long long ull;

namespace {
constexpr int Bn = 4096;
constexpr int Tn = 512;
constexpr int In = 5;
constexpr int Hn = 16;
constexpr int Gn = 4 * Hn;  // 64

constexpr int NTHREADS = 384;            // warp 0 = scan, warps 1..11 = workers
constexpr int NWORK    = NTHREADS - 32;  // 352
constexpr int CHUNK0_T = 64;             // rows ready before scan starts

// dynamic smem floats:
//   s_hb : 2 ping-pong bufs x 16 ull = 64 floats
//   s_xp : (Tn+1) rows x 16 lanes x 4 floats (xi',xf',xg',xo') = 32832
//   s_x, s_w, s_b, s_h
constexpr int HB_FLOATS = 64;
constexpr int XP_FLOATS = (Tn + 1) * 64;
constexpr int X_ELEMS   = Tn * In;
constexpr int W_ELEMS   = Gn * In;
constexpr int SMEM_FLOATS = HB_FLOATS + XP_FLOATS + X_ELEMS + W_ELEMS + Gn + Hn;
}

__device__ __forceinline__ float tanh_apx(float x) {
    float y;
    asm("tanh.approx.f32 %0, %1;" : "=f"(y) : "f"(x));
    return y;
}
__device__ __forceinline__ void fma2(ull& d, ull a, ull b, ull c) {
    asm("fma.rn.f32x2 %0, %1, %2, %3;" : "=l"(d) : "l"(a), "l"(b), "l"(c));
}
__device__ __forceinline__ void add2(ull& d, ull a, ull b) {
    asm("add.rn.f32x2 %0, %1, %2;" : "=l"(d) : "l"(a), "l"(b));
}
__device__ __forceinline__ ull pack2(float lo, float hi) {
    ull d;
    asm("mov.b64 %0, {%1, %2};" : "=l"(d) : "f"(lo), "f"(hi));
    return d;
}
__device__ __forceinline__ void unpack2(float& lo, float& hi, ull v) {
    asm("mov.b64 {%0, %1}, %2;" : "=f"(lo), "=f"(hi) : "l"(v));
}

__global__ __launch_bounds__(NTHREADS, 1)
void lstm_last_kernel(const float* __restrict__ x,
                      const float* __restrict__ Wih,
                      const float* __restrict__ Whh,
                      const float* __restrict__ bih,
                      const float* __restrict__ bhh,
                      const float* __restrict__ Wlin,
                      const float* __restrict__ blin,
                      float* __restrict__ out)
{
    extern __shared__ float smem[];
    float* s_hb = smem;                    // [2][16] (h,h) ull pairs
    float* s_xp = s_hb + HB_FLOATS;        // [Tn+1][16][4] gate quads
    float* s_x  = s_xp + XP_FLOATS;
    float* s_w  = s_x + X_ELEMS;
    float* s_b  = s_w + W_ELEMS;
    float* s_h  = s_b + Gn;

    __shared__ int s_flag0, s_flag1;       // chunk-ready flags

    const int tid = threadIdx.x;

    if (tid == 0) { s_flag0 = 0; s_flag1 = 0; }
    __syncthreads();   // only sync between scan warp and workers

    if (tid < 32) {
        // ================= SCAN WARP =================
        if (tid >= 16) return;             // lanes 16..31 idle
        const int ln = tid;

        // Pre-scaled joint weights (gmem; overlaps worker staging):
        //   Wif[k] = (0.5*W_i[ln][k], 0.5*W_f[ln][k])
        //   Wgo[k] = (    W_g[ln][k], 0.5*W_o[ln][k])
        ull Wif[Hn], Wgo[Hn];
        #pragma unroll
        for (int k = 0; k < Hn; k++) {
            Wif[k] = pack2(0.5f * Whh[ln * Hn + k],
                           0.5f * Whh[(16 + ln) * Hn + k]);
            Wgo[k] = pack2(Whh[(32 + ln) * Hn + k],
                           0.5f * Whh[(48 + ln) * Hn + k]);
        }
        // Prefetch output-layer params (lanes 0..4).
        float wl[Hn], bl = 0.0f;
        if (ln < 5) {
            bl = blin[ln];
            #pragma unroll
            for (int k = 0; k < Hn; k++) wl[k] = Wlin[ln * Hn + k];
        }

        ull* hb_base = (ull*)s_hb;
        const ulonglong2* xpq = (const ulonglong2*)s_xp;  // 16 per row

        // wait for xp chunk 0
        while (((volatile int*)&s_flag0)[0] == 0) { }
        __threadfence_block();

        float h = 0.0f, c = 0.0f;
        ulonglong2 xv = xpq[ln];           // row 0 quad: ((xi,xf),(xg,xo))

#define STEP(T)                                                            \
    {                                                                      \
        ull* HB = hb_base + (((T) & 1) << 4);                              \
        HB[ln] = pack2(h, h);                                              \
        asm volatile("" ::: "memory");                                     \
        const ulonglong2* hv = (const ulonglong2*)HB;                      \
        const ulonglong2 q0 = hv[0], q1 = hv[1], q2 = hv[2], q3 = hv[3];   \
        const ulonglong2 q4 = hv[4], q5 = hv[5], q6 = hv[6], q7 = hv[7];   \
        const ulonglong2 xn = xpq[((T) + 1) * 16 + ln];                    \
        ull p0 = xv.x, p1 = 0ull, p2 = 0ull, p3 = 0ull;                    \
        ull r0 = xv.y, r1 = 0ull, r2 = 0ull, r3 = 0ull;                    \
        fma2(p0, Wif[0],  q0.x, p0);  fma2(r0, Wgo[0],  q0.x, r0);         \
        fma2(p1, Wif[1],  q0.y, p1);  fma2(r1, Wgo[1],  q0.y, r1);         \
        fma2(p2, Wif[2],  q1.x, p2);  fma2(r2, Wgo[2],  q1.x, r2);         \
        fma2(p3, Wif[3],  q1.y, p3);  fma2(r3, Wgo[3],  q1.y, r3);         \
        fma2(p0, Wif[4],  q2.x, p0);  fma2(r0, Wgo[4],  q2.x, r0);         \
        fma2(p1, Wif[5],  q2.y, p1);  fma2(r1, Wgo[5],  q2.y, r1);         \
        fma2(p2, Wif[6],  q3.x, p2);  fma2(r2, Wgo[6],  q3.x, r2);         \
        fma2(p3, Wif[7],  q3.y, p3);  fma2(r3, Wgo[7],  q3.y, r3);         \
        fma2(p0, Wif[8],  q4.x, p0);  fma2(r0, Wgo[8],  q4.x, r0);         \
        fma2(p1, Wif[9],  q4.y, p1);  fma2(r1, Wgo[9],  q4.y, r1);         \
        fma2(p2, Wif[10], q5.x, p2);  fma2(r2, Wgo[10], q5.x, r2);         \
        fma2(p3, Wif[11], q5.y, p3);  fma2(r3, Wgo[11], q5.y, r3);         \
        fma2(p0, Wif[12], q6.x, p0);  fma2(r0, Wgo[12], q6.x, r0);         \
        fma2(p1, Wif[13], q6.y, p1);  fma2(r1, Wgo[13], q6.y, r1);         \
        fma2(p2, Wif[14], q7.x, p2);  fma2(r2, Wgo[14], q7.x, r2);         \
        fma2(p3, Wif[15], q7.y, p3);  fma2(r3, Wgo[15], q7.y, r3);         \
        add2(p0, p0, p1);  add2(p2, p2, p3);  add2(p0, p0, p2);            \
        add2(r0, r0, r1);  add2(r2, r2, r3);  add2(r0, r0, r2);            \
        float gi, gf, gg, go;                                              \
        unpack2(gi, gf, p0);  unpack2(gg, go, r0);                         \
        const float tg = tanh_apx(gg);                                     \
        const float si = fmaf(0.5f, tanh_apx(gi), 0.5f);                   \
        const float sf = fmaf(0.5f, tanh_apx(gf), 0.5f);                   \
        const float so = fmaf(0.5f, tanh_apx(go), 0.5f);                   \
        const float ig = si * tg;                                          \
        c = fmaf(sf, c, ig);                                               \
        h = so * tanh_apx(c);                                              \
        xv = xn;                                                           \
    }

        // steps 0..62 only touch rows 0..63 (step t prefetches row t+1)
        for (int t = 0; t < CHUNK0_T - 1; t++) STEP(t);
        while (((volatile int*)&s_flag1)[0] == 0) { }
        __threadfence_block();
        for (int t = CHUNK0_T - 1; t < Tn; t++) STEP(t);   // row Tn = pad
#undef STEP

        s_h[ln] = h;
        asm volatile("" ::: "memory");
        if (ln < 5) {
            float v = bl;
            #pragma unroll
            for (int k = 0; k < Hn; k++) v = fmaf(s_h[k], wl[k], v);
            out[ln] = fmaf(0.5f, tanh_apx(0.5f * v), 0.5f);
        }
        return;
    }

    // ================= WORKER WARPS (tid 32..383) =================
    const int wtid = tid - 32;

    // stage x (last batch row), W_ih, combined bias
    const float* xrow = x + (size_t)(Bn - 1) * Tn * In;
    for (int i = wtid; i < X_ELEMS; i += NWORK) s_x[i] = xrow[i];
    for (int i = wtid; i < W_ELEMS; i += NWORK) s_w[i] = Wih[i];
    if (wtid < Gn) s_b[wtid] = bih[wtid] + bhh[wtid];
    asm volatile("bar.sync 1, %0;" :: "n"(NWORK) : "memory");

    // xp quad layout: s_xp[t*64 + u*4 + gt], gt: 0=i(*.5) 1=f(*.5) 2=g 3=o(*.5)
    // chunk 0: rows [0, CHUNK0_T)
    for (int idx = wtid; idx < CHUNK0_T * Gn; idx += NWORK) {
        const int t = idx >> 6;
        const int g = idx & 63;
        const int gt = g >> 4, u = g & 15;
        const float* xr = s_x + t * In;
        const float* wr = s_w + g * In;
        float v = s_b[g];
        #pragma unroll
        for (int i = 0; i < In; i++) v = fmaf(xr[i], wr[i], v);
        s_xp[t * 64 + u * 4 + gt] = (gt == 2) ? v : 0.5f * v;
    }
    __threadfence_block();
    asm volatile("bar.sync 1, %0;" :: "n"(NWORK) : "memory");
    if (wtid == 0) { ((volatile int*)&s_flag0)[0] = 1; }

    // remaining rows + zero pad row Tn
    if (wtid < Gn) s_xp[Tn * 64 + wtid] = 0.0f;
    for (int idx = wtid + CHUNK0_T * Gn; idx < Tn * Gn; idx += NWORK) {
        const int t = idx >> 6;
        const int g = idx & 63;
        const int gt = g >> 4, u = g & 15;
        const float* xr = s_x + t * In;
        const float* wr = s_w + g * In;
        float v = s_b[g];
        #pragma unroll
        for (int i = 0; i < In; i++) v = fmaf(xr[i], wr[i], v);
        s_xp[t * 64 + u * 4 + gt] = (gt == 2) ? v : 0.5f * v;
    }
    __threadfence_block();
    asm volatile("bar.sync 1, %0;" :: "n"(NWORK) : "memory");
    if (wtid == 0) { ((volatile int*)&s_flag1)[0] = 1; }
}

extern "C" void kernel_launch(void* const* d_in, const int* in_sizes, int n_in,
                              void* d_out, int out_size)
{
    const float *x = nullptr, *Wih = nullptr, *Whh = nullptr;
    const float *bih = nullptr, *bhh = nullptr, *Wlin = nullptr, *blin = nullptr;
    for (int i = 0; i < n_in; i++) {
        const int s = in_sizes[i];
        const float* p = (const float*)d_in[i];
        if      (s == Bn * Tn * In) x    = p;
        else if (s == Gn * In)      Wih  = p;
        else if (s == Gn * Hn)      Whh  = p;
        else if (s == 5 * Hn)       Wlin = p;
        else if (s == Gn)           { if (!bih) bih = p; else bhh = p; }
        else if (s == 5)            blin = p;
    }

    const size_t smem_bytes = (size_t)SMEM_FLOATS * sizeof(float);
    cudaFuncSetAttribute(lstm_last_kernel,
                         cudaFuncAttributeMaxDynamicSharedMemorySize,
                         (int)smem_bytes);

    lstm_last_kernel<<<1, NTHREADS, smem_bytes>>>(
        x, Wih, Whh, bih, bhh, Wlin, blin, (float*)d_out);
}

// round 7
// speedup vs baseline: 1.2323x; 1.2323x over previous
#include <cuda_runtime.h>

// LSTM_71683004170991 — only batch element B-1 contributes to the output.
// R7 = R5 scan loop (split gates, 16 fma2, 2 shfls — issue floor below
// latency path) + re-timed c-update (shfl raw Ta, algebraic split) +
// Phase-1 overlapped with the scan via chunk-ready flags + Wlin prefetch.

#define FULLMASK 0xffffffffu
typedef unsigned long long ull;

namespace {
constexpr int Bn = 4096;
constexpr int Tn = 512;
constexpr int In = 5;
constexpr int Hn = 16;
constexpr int Gn = 4 * Hn;  // 64

constexpr int NTHREADS = 384;            // warp 0 = scan, warps 1..11 = workers
constexpr int NWORK    = NTHREADS - 32;  // 352
constexpr int CHUNK0_T = 64;             // xp rows ready before scan starts

constexpr int HB_FLOATS = 32;              // 2 ping-pong bufs x 16 floats
constexpr int XP_FLOATS = (Tn + 1) * 64;   // pair rows + zero pad row
constexpr int X_ELEMS   = Tn * In;
constexpr int W_ELEMS   = Gn * In;
constexpr int SMEM_FLOATS = HB_FLOATS + XP_FLOATS + X_ELEMS + W_ELEMS + Gn + Hn;
}

__device__ __forceinline__ float tanh_apx(float x) {
    float y;
    asm("tanh.approx.f32 %0, %1;" : "=f"(y) : "f"(x));
    return y;
}
__device__ __forceinline__ void fma2(ull& d, ull a, ull b, ull c) {
    asm("fma.rn.f32x2 %0, %1, %2, %3;" : "=l"(d) : "l"(a), "l"(b), "l"(c));
}
__device__ __forceinline__ void add2(ull& d, ull a, ull b) {
    asm("add.rn.f32x2 %0, %1, %2;" : "=l"(d) : "l"(a), "l"(b));
}
__device__ __forceinline__ ull pack2(float lo, float hi) {
    ull d;
    asm("mov.b64 %0, {%1, %2};" : "=l"(d) : "f"(lo), "f"(hi));
    return d;
}
__device__ __forceinline__ void unpack2(float& lo, float& hi, ull v) {
    asm("mov.b64 {%0, %1}, %2;" : "=f"(lo), "=f"(hi) : "l"(v));
}

__global__ __launch_bounds__(NTHREADS, 1)
void lstm_last_kernel(const float* __restrict__ x,
                      const float* __restrict__ Wih,
                      const float* __restrict__ Whh,
                      const float* __restrict__ bih,
                      const float* __restrict__ bhh,
                      const float* __restrict__ Wlin,
                      const float* __restrict__ blin,
                      float* __restrict__ out)
{
    extern __shared__ float smem[];
    float* s_hb = smem;                    // [2][16] h floats (unduplicated)
    float* s_xp = s_hb + HB_FLOATS;        // [Tn+1][32] (A,B) gate pairs
    float* s_x  = s_xp + XP_FLOATS;
    float* s_w  = s_x + X_ELEMS;
    float* s_b  = s_w + W_ELEMS;
    float* s_h  = s_b + Gn;

    __shared__ int s_flag0, s_flag1;

    const int tid = threadIdx.x;

    if (tid == 0) { s_flag0 = 0; s_flag1 = 0; }
    __syncthreads();

    if (tid < 32) {
        // ================= SCAN WARP =================
        const int lane = tid;
        const bool lo = lane < 16;

        // Paired-h weights (R5): WA[m]=(0.5Wa[2m],0.5Wa[2m+1]); B: g full / o half.
        const float sB = lo ? 1.0f : 0.5f;
        ull WA[8], WB[8];
        #pragma unroll
        for (int m = 0; m < 8; m++) {
            WA[m] = pack2(0.5f * Whh[lane * Hn + 2 * m],
                          0.5f * Whh[lane * Hn + 2 * m + 1]);
            WB[m] = pack2(sB * Whh[(32 + lane) * Hn + 2 * m],
                          sB * Whh[(32 + lane) * Hn + 2 * m + 1]);
        }
        // Prefetch output layer (lanes 0..4) — overlaps with worker staging.
        float wl[Hn], bl = 0.0f;
        if (lane < 5) {
            bl = blin[lane];
            #pragma unroll
            for (int k = 0; k < Hn; k++) wl[k] = Wlin[lane * Hn + k];
        }

        const ull* xpp = (const ull*)s_xp + lane;

        // wait for xp chunk 0
        while (((volatile int*)&s_flag0)[0] == 0) { }
        __threadfence_block();

        float h = 0.0f, c = 0.0f, halfc = 0.0f;
        float xa, xb;
        unpack2(xa, xb, xpp[0]);

#define STEP(T)                                                            \
    {                                                                      \
        float* HB = s_hb + (((T) & 1) << 4);                               \
        if (lo) HB[lane] = h;                                              \
        asm volatile("" ::: "memory");                                     \
        const ulonglong2* hv = (const ulonglong2*)HB;                      \
        const ulonglong2 q0 = hv[0], q1 = hv[1], q2 = hv[2], q3 = hv[3];   \
        const ull xp_next = xpp[((T) + 1) * 32];                           \
        ull a0 = pack2(xa, 0.0f), a1 = 0ull;                               \
        ull b0 = pack2(xb, 0.0f), b1 = 0ull;                               \
        fma2(a0, WA[0], q0.x, a0);  fma2(b0, WB[0], q0.x, b0);             \
        fma2(a1, WA[1], q0.y, a1);  fma2(b1, WB[1], q0.y, b1);             \
        fma2(a0, WA[2], q1.x, a0);  fma2(b0, WB[2], q1.x, b0);             \
        fma2(a1, WA[3], q1.y, a1);  fma2(b1, WB[3], q1.y, b1);             \
        fma2(a0, WA[4], q2.x, a0);  fma2(b0, WB[4], q2.x, b0);             \
        fma2(a1, WA[5], q2.y, a1);  fma2(b1, WB[5], q2.y, b1);             \
        fma2(a0, WA[6], q3.x, a0);  fma2(b0, WB[6], q3.x, b0);             \
        fma2(a1, WA[7], q3.y, a1);  fma2(b1, WB[7], q3.y, b1);             \
        add2(a0, a0, a1);  add2(b0, b0, b1);                               \
        float Axx, Ayy, Bxx, Byy;                                          \
        unpack2(Axx, Ayy, a0);  unpack2(Bxx, Byy, b0);                     \
        const float ga = Axx + Ayy;                                        \
        const float gb = Bxx + Byy;                                        \
        const float Ta = tanh_apx(ga);      /* lo: tanh(i/2); hi: tanh(f/2) */ \
        const float rt = __shfl_xor_sync(FULLMASK, Ta, 16); /* lo: Ta_f */ \
        const float Tb = tanh_apx(gb);      /* lo: tanh g ; hi: tanh(o/2) */ \
        const float b2 = fmaf(0.5f, Tb, 0.5f);                             \
        const float rb = __shfl_xor_sync(FULLMASK, b2, 16); /* lo: so */   \
        const float si = fmaf(0.5f, Ta, 0.5f);                             \
        const float ig = si * Tb;           /* lo: sigma(i)*tanh(g) */     \
        const float pre = fmaf(0.5f, c, ig);                               \
        c = fmaf(rt, halfc, pre);           /* = sf*c + ig on lo */        \
        halfc = 0.5f * c;                                                  \
        h = rb * tanh_apx(c);               /* lo: so*tanh(c) */           \
        unpack2(xa, xb, xp_next);                                          \
    }

        // steps 0..62 only touch rows 0..63 (step t prefetches row t+1)
        for (int t = 0; t < CHUNK0_T - 1; t++) STEP(t);
        while (((volatile int*)&s_flag1)[0] == 0) { }
        __threadfence_block();
        for (int t = CHUNK0_T - 1; t < Tn; t++) STEP(t);   // row Tn = pad
#undef STEP

        if (lo) s_h[lane] = h;
        asm volatile("" ::: "memory");
        if (lane < 5) {
            float v = bl;
            #pragma unroll
            for (int k = 0; k < Hn; k++) v = fmaf(s_h[k], wl[k], v);
            out[lane] = fmaf(0.5f, tanh_apx(0.5f * v), 0.5f);
        }
        return;
    }

    // ================= WORKER WARPS (tid 32..383) =================
    const int wtid = tid - 32;

    const float* xrow = x + (size_t)(Bn - 1) * Tn * In;
    for (int i = wtid; i < X_ELEMS; i += NWORK) s_x[i] = xrow[i];
    for (int i = wtid; i < W_ELEMS; i += NWORK) s_w[i] = Wih[i];
    if (wtid < Gn) s_b[wtid] = bih[wtid] + bhh[wtid];
    asm volatile("bar.sync 1, %0;" :: "n"(NWORK) : "memory");

    // xp pair layout (R5): s_xp[t*64 + (g&31)*2 + (g>>5)], sigmoid rows *0.5.
    for (int idx = wtid; idx < CHUNK0_T * Gn; idx += NWORK) {
        const int t = idx >> 6;
        const int g = idx & 63;
        const float* xr = s_x + t * In;
        const float* wr = s_w + g * In;
        float v = s_b[g];
        #pragma unroll
        for (int i = 0; i < In; i++) v = fmaf(xr[i], wr[i], v);
        const float sc = (g < 32 || g >= 48) ? 0.5f : 1.0f;
        s_xp[t * 64 + ((g & 31) << 1) + (g >> 5)] = v * sc;
    }
    __threadfence_block();
    asm volatile("bar.sync 1, %0;" :: "n"(NWORK) : "memory");
    if (wtid == 0) { ((volatile int*)&s_flag0)[0] = 1; }

    if (wtid < Gn) s_xp[Tn * 64 + wtid] = 0.0f;   // zero pad row
    for (int idx = wtid + CHUNK0_T * Gn; idx < Tn * Gn; idx += NWORK) {
        const int t = idx >> 6;
        const int g = idx & 63;
        const float* xr = s_x + t * In;
        const float* wr = s_w + g * In;
        float v = s_b[g];
        #pragma unroll
        for (int i = 0; i < In; i++) v = fmaf(xr[i], wr[i], v);
        const float sc = (g < 32 || g >= 48) ? 0.5f : 1.0f;
        s_xp[t * 64 + ((g & 31) << 1) + (g >> 5)] = v * sc;
    }
    __threadfence_block();
    asm volatile("bar.sync 1, %0;" :: "n"(NWORK) : "memory");
    if (wtid == 0) { ((volatile int*)&s_flag1)[0] = 1; }
}

extern "C" void kernel_launch(void* const* d_in, const int* in_sizes, int n_in,
                              void* d_out, int out_size)
{
    const float *x = nullptr, *Wih = nullptr, *Whh = nullptr;
    const float *bih = nullptr, *bhh = nullptr, *Wlin = nullptr, *blin = nullptr;
    for (int i = 0; i < n_in; i++) {
        const int s = in_sizes[i];
        const float* p = (const float*)d_in[i];
        if      (s == Bn * Tn * In) x    = p;
        else if (s == Gn * In)      Wih  = p;
        else if (s == Gn * Hn)      Whh  = p;
        else if (s == 5 * Hn)       Wlin = p;
        else if (s == Gn)           { if (!bih) bih = p; else bhh = p; }
        else if (s == 5)            blin = p;
    }

    const size_t smem_bytes = (size_t)SMEM_FLOATS * sizeof(float);
    cudaFuncSetAttribute(lstm_last_kernel,
                         cudaFuncAttributeMaxDynamicSharedMemorySize,
                         (int)smem_bytes);

    lstm_last_kernel<<<1, NTHREADS, smem_bytes>>>(
        x, Wih, Whh, bih, bhh, Wlin, blin, (float*)d_out);
}